// round 2
// baseline (speedup 1.0000x reference)
#include <cuda_runtime.h>
#include <float.h>
#include <math.h>

#define NCH 65536
#define BB  64
#define LL  512
#define DQK 64
#define MS  8
#define HID 128

// kproj[b][l][j][c] = sum_d k[b][l][d] * W1[64 + j*64 + d][c]
// 64*512*8*128 floats = 134 MB static device scratch (allowed; no allocation)
__device__ float g_kproj[(size_t)BB * LL * MS * HID];

// ---------------------------------------------------------------------------
// Kernel 1: kproj GEMM.  M = 32768 (b*512+l), K = 64, N = 8 slots x 128
// grid (512, 8), 256 threads, 64x128 output tile per CTA, K chunked by 32.
// ---------------------------------------------------------------------------
__global__ __launch_bounds__(256, 2) void kproj_kernel(
    const float* __restrict__ kmat, const float* __restrict__ W1)
{
    __shared__ float sA[64][36];   // 64 rows x 32 K (+4 pad)
    __shared__ float sB[32][128];  // 32 K x 128 cols

    const int tid = threadIdx.x;
    const int m0  = blockIdx.x * 64;
    const int j   = blockIdx.y;
    const int tr  = tid >> 4;      // 0..15 -> 4 rows each
    const int tc  = tid & 15;      // 0..15 -> 8 cols each

    float acc[4][8];
#pragma unroll
    for (int i = 0; i < 4; i++)
#pragma unroll
        for (int u = 0; u < 8; u++) acc[i][u] = 0.f;

#pragma unroll
    for (int kc = 0; kc < 2; kc++) {
        // load A chunk: 64x32 floats = 512 float4
#pragma unroll
        for (int s = 0; s < 2; s++) {
            int f = tid + 256 * s;
            int r = f >> 3, c4 = f & 7;
            float4 v = *reinterpret_cast<const float4*>(
                kmat + (size_t)(m0 + r) * 64 + kc * 32 + c4 * 4);
            *reinterpret_cast<float4*>(&sA[r][c4 * 4]) = v;
        }
        // load W1 chunk: rows 64 + j*64 + kc*32 + d, d=0..31, 128 cols
#pragma unroll
        for (int s = 0; s < 4; s++) {
            int f = tid + 256 * s;
            int d = f >> 5, c4 = f & 31;
            *reinterpret_cast<float4*>(&sB[d][c4 * 4]) =
                *reinterpret_cast<const float4*>(
                    W1 + (size_t)(64 + j * 64 + kc * 32 + d) * 128 + c4 * 4);
        }
        __syncthreads();
#pragma unroll
        for (int kk = 0; kk < 32; kk++) {
            float ra[4];
#pragma unroll
            for (int i = 0; i < 4; i++) ra[i] = sA[tr * 4 + i][kk];
            float4 w0 = *reinterpret_cast<const float4*>(&sB[kk][tc * 8]);
            float4 w1 = *reinterpret_cast<const float4*>(&sB[kk][tc * 8 + 4]);
            float rb[8] = {w0.x, w0.y, w0.z, w0.w, w1.x, w1.y, w1.z, w1.w};
#pragma unroll
            for (int i = 0; i < 4; i++)
#pragma unroll
                for (int u = 0; u < 8; u++)
                    acc[i][u] = fmaf(ra[i], rb[u], acc[i][u]);
        }
        __syncthreads();
    }

#pragma unroll
    for (int i = 0; i < 4; i++) {
        size_t m = (size_t)(m0 + tr * 4 + i);
        float* o = g_kproj + (m * 8 + j) * 128 + tc * 8;
        float4 o0 = {acc[i][0], acc[i][1], acc[i][2], acc[i][3]};
        float4 o1 = {acc[i][4], acc[i][5], acc[i][6], acc[i][7]};
        *reinterpret_cast<float4*>(o)     = o0;
        *reinterpret_cast<float4*>(o + 4) = o1;
    }
}

// ---------------------------------------------------------------------------
// Kernel 2: per-chain: top-8 selection, q@W1q GEMM, kproj gather, gelu, @W2.
// grid 1024, 256 threads, 64 chains per CTA.
// mask is read as 32-bit words (nonzero test): robust to int32 0/1 and
// float32 0.0/1.0 encodings of the original bool array.
// ---------------------------------------------------------------------------
__global__ __launch_bounds__(256, 2) void chain_kernel(
    const float* __restrict__ q,
    const int*   __restrict__ batch_idx,
    const int*   __restrict__ mask,
    const int*   __restrict__ count,
    const float* __restrict__ rank,
    const float* __restrict__ W1,
    const float* __restrict__ b1,
    const float* __restrict__ W2,
    const float* __restrict__ b2,
    float* __restrict__ out)
{
    __shared__ float sA[64][36];      // q chunk 64x32 (+pad)
    __shared__ float sB[32][128];     // W1q chunk
    __shared__ float sW1last[128], sB1[128], sW2[128];
    __shared__ int   sIdx[64][8];
    __shared__ int   sN[64], sBatch[64];
    __shared__ float sLogc[64];

    const int tid = threadIdx.x;
    const int c0  = blockIdx.x * 64;

    if (tid < 128) {
        sW1last[tid] = W1[576 * 128 + tid];
        sB1[tid]     = b1[tid];
        sW2[tid]     = W2[tid];
    }
    if (tid < 64) {
        sBatch[tid] = batch_idx[c0 + tid];
        sLogc[tid]  = log1pf((float)count[c0 + tid]);
    }

    // ---- Phase 1: top-8 selection (warp w handles chains w*8 .. w*8+7) ----
    const int w = tid >> 5, lane = tid & 31;
    for (int ci = 0; ci < 8; ci++) {
        const int cl    = w * 8 + ci;
        const int chain = c0 + cl;
        const float* sc = rank + (size_t)chain * 512 + lane * 16;
        const int4*  mk = reinterpret_cast<const int4*>(mask + (size_t)chain * 512) + lane * 4;

        float v[16];
        int localcnt = 0;
#pragma unroll
        for (int g = 0; g < 4; g++) {
            int4  mw = mk[g];
            float4 s = *reinterpret_cast<const float4*>(sc + g * 4);
            int   me[4] = {mw.x, mw.y, mw.z, mw.w};
            float vv[4] = {s.x, s.y, s.z, s.w};
#pragma unroll
            for (int e = 0; e < 4; e++) {
                bool mm = (me[e] != 0);
                v[g * 4 + e] = mm ? vv[e] : -FLT_MAX;
                localcnt += mm ? 1 : 0;
            }
        }
        int m_total = __reduce_add_sync(0xffffffffu, localcnt);
        int nsel = m_total < 8 ? m_total : 8;

        int ids[8];
#pragma unroll
        for (int t = 0; t < 8; t++) {
            float bv = v[0]; int bi = 0;
#pragma unroll
            for (int i2 = 1; i2 < 16; i2++)
                if (v[i2] > bv) { bv = v[i2]; bi = i2; }
            int bpos = lane * 16 + bi;
#pragma unroll
            for (int off = 16; off; off >>= 1) {
                float ov = __shfl_xor_sync(0xffffffffu, bv, off);
                int   op = __shfl_xor_sync(0xffffffffu, bpos, off);
                if (ov > bv || (ov == bv && op < bpos)) { bv = ov; bpos = op; }
            }
            if ((bpos >> 4) == lane) v[bpos & 15] = -FLT_MAX;  // invalidate winner
            ids[t] = bpos;
        }
        // drop slots beyond the number of valid (masked) picks, sort ascending
#pragma unroll
        for (int t = 0; t < 8; t++) if (t >= nsel) ids[t] = 1 << 20;
#pragma unroll
        for (int a = 0; a < 7; a++)
#pragma unroll
            for (int bq = 0; bq < 7 - a; bq++)
                if (ids[bq] > ids[bq + 1]) {
                    int tmp = ids[bq]; ids[bq] = ids[bq + 1]; ids[bq + 1] = tmp;
                }
        if (lane == 0) {
#pragma unroll
            for (int t = 0; t < 8; t++) sIdx[cl][t] = ids[t];
            sN[cl] = nsel;
        }
    }
    __syncthreads();

    // ---- Phase 2: q @ W1[0:64] GEMM (acc initialized with b1) ----
    const int tr = tid >> 4, tc = tid & 15;
    float acc[4][8];
#pragma unroll
    for (int i = 0; i < 4; i++)
#pragma unroll
        for (int u = 0; u < 8; u++) acc[i][u] = sB1[tc * 8 + u];

#pragma unroll
    for (int kc = 0; kc < 2; kc++) {
#pragma unroll
        for (int s = 0; s < 2; s++) {
            int f = tid + 256 * s;
            int r = f >> 3, c4 = f & 7;
            float4 vv = *reinterpret_cast<const float4*>(
                q + (size_t)(c0 + r) * 64 + kc * 32 + c4 * 4);
            *reinterpret_cast<float4*>(&sA[r][c4 * 4]) = vv;
        }
#pragma unroll
        for (int s = 0; s < 4; s++) {
            int f = tid + 256 * s;
            int d = f >> 5, c4 = f & 31;
            *reinterpret_cast<float4*>(&sB[d][c4 * 4]) =
                *reinterpret_cast<const float4*>(
                    W1 + (size_t)(kc * 32 + d) * 128 + c4 * 4);
        }
        __syncthreads();
#pragma unroll
        for (int kk = 0; kk < 32; kk++) {
            float ra[4];
#pragma unroll
            for (int i = 0; i < 4; i++) ra[i] = sA[tr * 4 + i][kk];
            float4 w0 = *reinterpret_cast<const float4*>(&sB[kk][tc * 8]);
            float4 w1 = *reinterpret_cast<const float4*>(&sB[kk][tc * 8 + 4]);
            float rb[8] = {w0.x, w0.y, w0.z, w0.w, w1.x, w1.y, w1.z, w1.w};
#pragma unroll
            for (int i = 0; i < 4; i++)
#pragma unroll
                for (int u = 0; u < 8; u++)
                    acc[i][u] = fmaf(ra[i], rb[u], acc[i][u]);
        }
        __syncthreads();
    }

    // ---- Phase 3: gather precomputed kproj slot vectors + log-count term ----
    float wl[8];
#pragma unroll
    for (int u = 0; u < 8; u++) wl[u] = sW1last[tc * 8 + u];

#pragma unroll
    for (int i = 0; i < 4; i++) {
        const int cl = tr * 4 + i;
        const int n  = sN[cl];
        const int bb = sBatch[cl];
        const float lc = sLogc[cl];
#pragma unroll
        for (int u = 0; u < 8; u++) acc[i][u] = fmaf(lc, wl[u], acc[i][u]);
        for (int jj = 0; jj < n; jj++) {
            size_t base = (((size_t)bb * 512 + sIdx[cl][jj]) * 8 + jj) * 128 + tc * 8;
            float4 g0 = *reinterpret_cast<const float4*>(g_kproj + base);
            float4 g1 = *reinterpret_cast<const float4*>(g_kproj + base + 4);
            acc[i][0] += g0.x; acc[i][1] += g0.y; acc[i][2] += g0.z; acc[i][3] += g0.w;
            acc[i][4] += g1.x; acc[i][5] += g1.y; acc[i][6] += g1.z; acc[i][7] += g1.w;
        }
    }

    // ---- Phase 4: exact gelu ----
#pragma unroll
    for (int i = 0; i < 4; i++)
#pragma unroll
        for (int u = 0; u < 8; u++) {
            float x = acc[i][u];
            acc[i][u] = 0.5f * x * (1.0f + erff(x * 0.70710678118654752440f));
        }

    // ---- Phase 5: h @ W2 + b2, reduce across the 16 col-threads ----
    const float b2v = b2[0];
#pragma unroll
    for (int i = 0; i < 4; i++) {
        float p = 0.f;
#pragma unroll
        for (int u = 0; u < 8; u++) p = fmaf(acc[i][u], sW2[tc * 8 + u], p);
#pragma unroll
        for (int off = 8; off; off >>= 1)
            p += __shfl_down_sync(0xffffffffu, p, off, 16);
        if (tc == 0) out[c0 + tr * 4 + i] = p + b2v;
    }
}

// ---------------------------------------------------------------------------
extern "C" void kernel_launch(void* const* d_in, const int* in_sizes, int n_in,
                              void* d_out, int out_size)
{
    const float* q         = (const float*)d_in[0];
    const float* kmat      = (const float*)d_in[1];
    const int*   batch_idx = (const int*)d_in[2];
    const int*   mask      = (const int*)d_in[3];
    const int*   count     = (const int*)d_in[4];
    const float* rank      = (const float*)d_in[5];
    const float* W1        = (const float*)d_in[6];
    const float* b1        = (const float*)d_in[7];
    const float* W2        = (const float*)d_in[8];
    const float* b2        = (const float*)d_in[9];
    float* out = (float*)d_out;

    kproj_kernel<<<dim3(512, 8), 256>>>(kmat, W1);
    chain_kernel<<<1024, 256>>>(q, batch_idx, mask, count, rank,
                                W1, b1, W2, b2, out);
}

// round 3
// speedup vs baseline: 1.0160x; 1.0160x over previous
#include <cuda_runtime.h>
#include <float.h>
#include <math.h>

#define NCH 65536
#define BB  64
#define LL  512
#define DQK 64
#define MS  8
#define HID 128

// kproj[b][l][j][c] = sum_d k[b][l][d] * W1[64 + j*64 + d][c]   (134 MB)
__device__ float g_kproj[(size_t)BB * LL * MS * HID];
// selection results
__device__ int g_selidx[(size_t)NCH * MS];
__device__ int g_seln[NCH];

// order-preserving float->u32 (monotonic); masked entries use 0
__device__ __forceinline__ unsigned f2u(float f) {
    unsigned u = __float_as_uint(f);
    return (u & 0x80000000u) ? ~u : (u | 0x80000000u);
}

// ---------------------------------------------------------------------------
// Kernel 1 (fused): 4608 CTAs. bx%9==8 -> selection (512 CTAs), else kproj
// tile (4096 CTAs). Disjoint pipes (FFMA vs DRAM/MIO) overlap across SMs.
// ---------------------------------------------------------------------------
__global__ __launch_bounds__(256, 2) void fused1_kernel(
    const float* __restrict__ kmat, const float* __restrict__ W1,
    const int* __restrict__ mask, const float* __restrict__ rank)
{
    const int bx  = blockIdx.x;
    const int tid = threadIdx.x;

    if (bx % 9 == 8) {
        // ================= selection path: 8 warps, 16 chains per warp ====
        const int sb   = bx / 9;                  // 0..511
        const int w    = tid >> 5, lane = tid & 31;
        const unsigned full = 0xffffffffu;

        for (int cc = 0; cc < 16; cc++) {
            const int chain = (sb * 8 + w) * 16 + cc;
            const float* sc = rank + (size_t)chain * 512 + lane * 16;
            const int4*  mk = reinterpret_cast<const int4*>(
                                  mask + (size_t)chain * 512) + lane * 4;

            unsigned key[16];
            int cnt = 0;
#pragma unroll
            for (int g = 0; g < 4; g++) {
                int4   mw = mk[g];
                float4 s  = *reinterpret_cast<const float4*>(sc + g * 4);
                int   me[4] = {mw.x, mw.y, mw.z, mw.w};
                float vv[4] = {s.x, s.y, s.z, s.w};
#pragma unroll
                for (int e = 0; e < 4; e++) {
                    bool mm = (me[e] != 0);
                    key[g * 4 + e] = mm ? f2u(vv[e]) : 0u;
                    cnt += mm ? 1 : 0;
                }
            }
            int tot  = __reduce_add_sync(full, cnt);
            int nsel = tot < 8 ? tot : 8;

            // local running max
            unsigned lmax = 0; int lpos = 0;
#pragma unroll
            for (int i = 0; i < 16; i++)
                if (key[i] > lmax) { lmax = key[i]; lpos = i; }

            int ids[8];
#pragma unroll
            for (int t = 0; t < 8; t++) {
                unsigned m   = __reduce_max_sync(full, lmax);
                unsigned bal = __ballot_sync(full, lmax == m);
                int src  = __ffs(bal) - 1;
                int gpos = __shfl_sync(full, lane * 16 + lpos, src);
                ids[t] = gpos;
                if (lane == src) {          // winner invalidates + rescans
                    key[lpos] = 0;
                    lmax = 0; lpos = 0;
#pragma unroll
                    for (int i = 0; i < 16; i++)
                        if (key[i] > lmax) { lmax = key[i]; lpos = i; }
                }
            }
#pragma unroll
            for (int t = 0; t < 8; t++) if (t >= nsel) ids[t] = 1 << 20;
#pragma unroll
            for (int a = 0; a < 7; a++)
#pragma unroll
                for (int bq = 0; bq < 7 - a; bq++)
                    if (ids[bq] > ids[bq + 1]) {
                        int tmp = ids[bq]; ids[bq] = ids[bq + 1]; ids[bq + 1] = tmp;
                    }
            if (lane == 0) {
                int4 o0 = {ids[0], ids[1], ids[2], ids[3]};
                int4 o1 = {ids[4], ids[5], ids[6], ids[7]};
                *reinterpret_cast<int4*>(g_selidx + (size_t)chain * 8)     = o0;
                *reinterpret_cast<int4*>(g_selidx + (size_t)chain * 8 + 4) = o1;
                g_seln[chain] = nsel;
            }
        }
        return;
    }

    // ================= kproj path ========================================
    __shared__ float sA[64][36];
    __shared__ float sB[32][128];

    const int kidx = bx - bx / 9;          // 0..4095
    const int m0   = (kidx & 511) * 64;
    const int j    = kidx >> 9;
    const int tr   = tid >> 4;
    const int tc   = tid & 15;

    float acc[4][8];
#pragma unroll
    for (int i = 0; i < 4; i++)
#pragma unroll
        for (int u = 0; u < 8; u++) acc[i][u] = 0.f;

#pragma unroll
    for (int kc = 0; kc < 2; kc++) {
#pragma unroll
        for (int s = 0; s < 2; s++) {
            int f = tid + 256 * s;
            int r = f >> 3, c4 = f & 7;
            float4 v = *reinterpret_cast<const float4*>(
                kmat + (size_t)(m0 + r) * 64 + kc * 32 + c4 * 4);
            *reinterpret_cast<float4*>(&sA[r][c4 * 4]) = v;
        }
#pragma unroll
        for (int s = 0; s < 4; s++) {
            int f = tid + 256 * s;
            int d = f >> 5, c4 = f & 31;
            *reinterpret_cast<float4*>(&sB[d][c4 * 4]) =
                *reinterpret_cast<const float4*>(
                    W1 + (size_t)(64 + j * 64 + kc * 32 + d) * 128 + c4 * 4);
        }
        __syncthreads();
#pragma unroll
        for (int kk = 0; kk < 32; kk++) {
            float ra[4];
#pragma unroll
            for (int i = 0; i < 4; i++) ra[i] = sA[tr * 4 + i][kk];
            float4 w0 = *reinterpret_cast<const float4*>(&sB[kk][tc * 8]);
            float4 w1 = *reinterpret_cast<const float4*>(&sB[kk][tc * 8 + 4]);
            float rb[8] = {w0.x, w0.y, w0.z, w0.w, w1.x, w1.y, w1.z, w1.w};
#pragma unroll
            for (int i = 0; i < 4; i++)
#pragma unroll
                for (int u = 0; u < 8; u++)
                    acc[i][u] = fmaf(ra[i], rb[u], acc[i][u]);
        }
        __syncthreads();
    }

#pragma unroll
    for (int i = 0; i < 4; i++) {
        size_t m = (size_t)(m0 + tr * 4 + i);
        float* o = g_kproj + (m * 8 + j) * 128 + tc * 8;
        float4 o0 = {acc[i][0], acc[i][1], acc[i][2], acc[i][3]};
        float4 o1 = {acc[i][4], acc[i][5], acc[i][6], acc[i][7]};
        *reinterpret_cast<float4*>(o)     = o0;
        *reinterpret_cast<float4*>(o + 4) = o1;
    }
}

// ---------------------------------------------------------------------------
// Kernel 2: MLP per chain: q@W1q GEMM, kproj gather, gelu, @W2.
// grid 1024 x 256 threads, 64 chains per CTA.
// ---------------------------------------------------------------------------
__global__ __launch_bounds__(256, 2) void chain_kernel(
    const float* __restrict__ q,
    const int*   __restrict__ batch_idx,
    const int*   __restrict__ count,
    const float* __restrict__ W1,
    const float* __restrict__ b1,
    const float* __restrict__ W2,
    const float* __restrict__ b2,
    float* __restrict__ out)
{
    __shared__ float sA[64][36];
    __shared__ float sB[32][128];
    __shared__ float sW1last[128], sB1[128], sW2[128];
    __shared__ int   sIdx[64][8];
    __shared__ int   sN[64], sBatch[64];
    __shared__ float sLogc[64];

    const int tid = threadIdx.x;
    const int c0  = blockIdx.x * 64;

    if (tid < 128) {
        sW1last[tid] = W1[576 * 128 + tid];
        sB1[tid]     = b1[tid];
        sW2[tid]     = W2[tid];
    }
    if (tid < 64) {
        sBatch[tid] = batch_idx[c0 + tid];
        sLogc[tid]  = log1pf((float)count[c0 + tid]);
        sN[tid]     = g_seln[c0 + tid];
    }
    {   // 64 chains x 8 ids = 512 ints, 2 per thread
        int f = tid;
        sIdx[f >> 2][(f & 3) * 2]     = g_selidx[(size_t)c0 * 8 + f * 2];
        sIdx[f >> 2][(f & 3) * 2 + 1] = g_selidx[(size_t)c0 * 8 + f * 2 + 1];
    }

    // ---- q @ W1[0:64] GEMM (acc initialized with b1) ----
    const int tr = tid >> 4, tc = tid & 15;
    float acc[4][8];
#pragma unroll
    for (int i = 0; i < 4; i++)
#pragma unroll
        for (int u = 0; u < 8; u++) acc[i][u] = 0.f;   // b1 added later via sB1

#pragma unroll
    for (int kc = 0; kc < 2; kc++) {
#pragma unroll
        for (int s = 0; s < 2; s++) {
            int f = tid + 256 * s;
            int r = f >> 3, c4 = f & 7;
            float4 vv = *reinterpret_cast<const float4*>(
                q + (size_t)(c0 + r) * 64 + kc * 32 + c4 * 4);
            *reinterpret_cast<float4*>(&sA[r][c4 * 4]) = vv;
        }
#pragma unroll
        for (int s = 0; s < 4; s++) {
            int f = tid + 256 * s;
            int d = f >> 5, c4 = f & 31;
            *reinterpret_cast<float4*>(&sB[d][c4 * 4]) =
                *reinterpret_cast<const float4*>(
                    W1 + (size_t)(kc * 32 + d) * 128 + c4 * 4);
        }
        __syncthreads();
#pragma unroll
        for (int kk = 0; kk < 32; kk++) {
            float ra[4];
#pragma unroll
            for (int i = 0; i < 4; i++) ra[i] = sA[tr * 4 + i][kk];
            float4 w0 = *reinterpret_cast<const float4*>(&sB[kk][tc * 8]);
            float4 w1 = *reinterpret_cast<const float4*>(&sB[kk][tc * 8 + 4]);
            float rb[8] = {w0.x, w0.y, w0.z, w0.w, w1.x, w1.y, w1.z, w1.w};
#pragma unroll
            for (int i = 0; i < 4; i++)
#pragma unroll
                for (int u = 0; u < 8; u++)
                    acc[i][u] = fmaf(ra[i], rb[u], acc[i][u]);
        }
        __syncthreads();
    }

    // ---- bias + log-count term + kproj gather ----
    float wl[8], bb1[8];
#pragma unroll
    for (int u = 0; u < 8; u++) {
        wl[u]  = sW1last[tc * 8 + u];
        bb1[u] = sB1[tc * 8 + u];
    }

#pragma unroll
    for (int i = 0; i < 4; i++) {
        const int cl = tr * 4 + i;
        const int n  = sN[cl];
        const int bb = sBatch[cl];
        const float lc = sLogc[cl];
#pragma unroll
        for (int u = 0; u < 8; u++)
            acc[i][u] = acc[i][u] + bb1[u] + lc * wl[u];
        for (int jj = 0; jj < n; jj++) {
            size_t base = (((size_t)bb * 512 + sIdx[cl][jj]) * 8 + jj) * 128 + tc * 8;
            float4 g0 = *reinterpret_cast<const float4*>(g_kproj + base);
            float4 g1 = *reinterpret_cast<const float4*>(g_kproj + base + 4);
            acc[i][0] += g0.x; acc[i][1] += g0.y; acc[i][2] += g0.z; acc[i][3] += g0.w;
            acc[i][4] += g1.x; acc[i][5] += g1.y; acc[i][6] += g1.z; acc[i][7] += g1.w;
        }
    }

    // ---- exact gelu ----
#pragma unroll
    for (int i = 0; i < 4; i++)
#pragma unroll
        for (int u = 0; u < 8; u++) {
            float x = acc[i][u];
            acc[i][u] = 0.5f * x * (1.0f + erff(x * 0.70710678118654752440f));
        }

    // ---- h @ W2 + b2, reduce across 16 col-threads ----
    const float b2v = b2[0];
#pragma unroll
    for (int i = 0; i < 4; i++) {
        float p = 0.f;
#pragma unroll
        for (int u = 0; u < 8; u++) p = fmaf(acc[i][u], sW2[tc * 8 + u], p);
#pragma unroll
        for (int off = 8; off; off >>= 1)
            p += __shfl_down_sync(0xffffffffu, p, off, 16);
        if (tc == 0) out[c0 + tr * 4 + i] = p + b2v;
    }
}

// ---------------------------------------------------------------------------
extern "C" void kernel_launch(void* const* d_in, const int* in_sizes, int n_in,
                              void* d_out, int out_size)
{
    const float* q         = (const float*)d_in[0];
    const float* kmat      = (const float*)d_in[1];
    const int*   batch_idx = (const int*)d_in[2];
    const int*   mask      = (const int*)d_in[3];
    const int*   count     = (const int*)d_in[4];
    const float* rank      = (const float*)d_in[5];
    const float* W1        = (const float*)d_in[6];
    const float* b1        = (const float*)d_in[7];
    const float* W2        = (const float*)d_in[8];
    const float* b2        = (const float*)d_in[9];
    float* out = (float*)d_out;

    fused1_kernel<<<4608, 256>>>(kmat, W1, mask, rank);
    chain_kernel<<<1024, 256>>>(q, batch_idx, count, W1, b1, W2, b2, out);
}

// round 5
// speedup vs baseline: 1.1901x; 1.1713x over previous
#include <cuda_runtime.h>
#include <cuda_bf16.h>
#include <mma.h>
#include <float.h>
#include <math.h>
#include <stdint.h>

#define NCH 65536
#define BB  64
#define LL  512
#define MS  8
#define HID 128

__device__ float g_kproj[(size_t)BB * LL * MS * HID];   // 134 MB scratch
__device__ int   g_selidx[(size_t)NCH * MS];
__device__ int   g_seln[NCH];

// order-preserving float->u32 (monotonic); masked entries use 0
__device__ __forceinline__ unsigned f2u(float f) {
    unsigned u = __float_as_uint(f);
    return (u & 0x80000000u) ? ~u : (u | 0x80000000u);
}

// ---------------------------------------------------------------------------
// Kernel 0: top-8 selection. grid 512 x 256 thr; warp handles 16 chains.
// All register-resident (static indexing only -> no local memory).
// ---------------------------------------------------------------------------
__global__ __launch_bounds__(256) void select_kernel(
    const int* __restrict__ mask, const float* __restrict__ rank)
{
    const int tid = threadIdx.x;
    const int w = tid >> 5, lane = tid & 31;
    const unsigned full = 0xffffffffu;

    for (int cc = 0; cc < 16; cc++) {
        const int chain = (blockIdx.x * 8 + w) * 16 + cc;
        const float* sc = rank + (size_t)chain * 512 + lane * 16;
        const int4*  mk = reinterpret_cast<const int4*>(
                              mask + (size_t)chain * 512) + lane * 4;
        unsigned key[16];
        int cnt = 0;
#pragma unroll
        for (int g = 0; g < 4; g++) {
            int4   mw = mk[g];
            float4 s  = *reinterpret_cast<const float4*>(sc + g * 4);
            int   me[4] = {mw.x, mw.y, mw.z, mw.w};
            float vv[4] = {s.x, s.y, s.z, s.w};
#pragma unroll
            for (int e = 0; e < 4; e++) {
                bool mm = (me[e] != 0);
                key[g * 4 + e] = mm ? f2u(vv[e]) : 0u;
                cnt += mm ? 1 : 0;
            }
        }
        int tot  = __reduce_add_sync(full, cnt);
        int nsel = tot < 8 ? tot : 8;

        unsigned lmax = 0; int lpos = 0;
#pragma unroll
        for (int i = 0; i < 16; i++)
            if (key[i] > lmax) { lmax = key[i]; lpos = i; }

        int ids[8];
#pragma unroll
        for (int t = 0; t < 8; t++) {
            unsigned m   = __reduce_max_sync(full, lmax);
            unsigned bal = __ballot_sync(full, lmax == m);
            int src  = __ffs(bal) - 1;
            int gpos = __shfl_sync(full, lane * 16 + lpos, src);
            ids[t] = gpos;
            if (lane == src) {   // static-index clear + rescan (registers only)
                unsigned nmax = 0; int npos = 0;
#pragma unroll
                for (int i = 0; i < 16; i++) {
                    unsigned ki = (i == lpos) ? 0u : key[i];
                    key[i] = ki;
                    if (ki > nmax) { nmax = ki; npos = i; }
                }
                lmax = nmax; lpos = npos;
            }
        }
#pragma unroll
        for (int t = 0; t < 8; t++) if (t >= nsel) ids[t] = 1 << 20;
#pragma unroll
        for (int a = 0; a < 7; a++)
#pragma unroll
            for (int bq = 0; bq < 7 - a; bq++)
                if (ids[bq] > ids[bq + 1]) {
                    int tmp = ids[bq]; ids[bq] = ids[bq + 1]; ids[bq + 1] = tmp;
                }
        if (lane == 0) {
            int4 o0 = {ids[0], ids[1], ids[2], ids[3]};
            int4 o1 = {ids[4], ids[5], ids[6], ids[7]};
            *reinterpret_cast<int4*>(g_selidx + (size_t)chain * 8)     = o0;
            *reinterpret_cast<int4*>(g_selidx + (size_t)chain * 8 + 4) = o1;
            g_seln[chain] = nsel;
        }
    }
}

// ---------------------------------------------------------------------------
// Kernel 1: kproj via WMMA bf16x3 (Ahi*Bhi + Ahi*Blo + Alo*Bhi, fp32 acc).
// grid (256, 8), 256 threads. Per CTA: 128 k-rows x 128 cols of slot j, K=64.
// ---------------------------------------------------------------------------
#define A_LD 72          // 64 + 8 pad (bf16 elems)
#define B_LD 136         // 128 + 8 pad
#define OFF_AHI 0
#define OFF_ALO 18432    // 128*72*2
#define OFF_BHI 36864
#define OFF_BLO 54272    // + 64*136*2
#define KP_SMEM 71680
#define STG_LD  132      // f32 staging leading dim

using namespace nvcuda;

__global__ __launch_bounds__(256) void kproj_wmma_kernel(
    const float* __restrict__ kmat, const float* __restrict__ W1)
{
    extern __shared__ char smem[];
    __nv_bfloat16* Ah = reinterpret_cast<__nv_bfloat16*>(smem + OFF_AHI);
    __nv_bfloat16* Al = reinterpret_cast<__nv_bfloat16*>(smem + OFF_ALO);
    __nv_bfloat16* Bh = reinterpret_cast<__nv_bfloat16*>(smem + OFF_BHI);
    __nv_bfloat16* Bl = reinterpret_cast<__nv_bfloat16*>(smem + OFF_BLO);

    const int tid = threadIdx.x;
    const int m0  = blockIdx.x * 128;
    const int j   = blockIdx.y;

    // --- fill A (k rows, hi/lo split): 128x64 floats = 2048 float4
    for (int idx = tid; idx < 2048; idx += 256) {
        int r = idx >> 4, c4 = idx & 15;
        float4 v = *reinterpret_cast<const float4*>(
            kmat + (size_t)(m0 + r) * 64 + c4 * 4);
        float f[4] = {v.x, v.y, v.z, v.w};
#pragma unroll
        for (int e = 0; e < 4; e++) {
            __nv_bfloat16 hi = __float2bfloat16(f[e]);
            Ah[r * A_LD + c4 * 4 + e] = hi;
            Al[r * A_LD + c4 * 4 + e] = __float2bfloat16(f[e] - __bfloat162float(hi));
        }
    }
    // --- fill B (W1 slot j rows 64+j*64+k, hi/lo): 64x128 floats = 2048 float4
    for (int idx = tid; idx < 2048; idx += 256) {
        int r = idx >> 5, c4 = idx & 31;
        float4 v = *reinterpret_cast<const float4*>(
            W1 + (size_t)(64 + j * 64 + r) * 128 + c4 * 4);
        float f[4] = {v.x, v.y, v.z, v.w};
#pragma unroll
        for (int e = 0; e < 4; e++) {
            __nv_bfloat16 hi = __float2bfloat16(f[e]);
            Bh[r * B_LD + c4 * 4 + e] = hi;
            Bl[r * B_LD + c4 * 4 + e] = __float2bfloat16(f[e] - __bfloat162float(hi));
        }
    }
    __syncthreads();

    // --- compute: warp grid 4(M) x 2(N); warp tile 32x64 = 2x4 wmma tiles
    const int w  = tid >> 5;
    const int wm = w >> 1, wn = w & 1;

    wmma::fragment<wmma::accumulator, 16, 16, 16, float> acc[2][4];
#pragma unroll
    for (int i = 0; i < 2; i++)
#pragma unroll
        for (int jn = 0; jn < 4; jn++) wmma::fill_fragment(acc[i][jn], 0.f);

#pragma unroll
    for (int pass = 0; pass < 3; pass++) {
        const __nv_bfloat16* Ap = (pass == 2) ? Al : Ah;
        const __nv_bfloat16* Bp = (pass == 1) ? Bl : Bh;
#pragma unroll
        for (int k0 = 0; k0 < 64; k0 += 16) {
            wmma::fragment<wmma::matrix_a, 16, 16, 16, __nv_bfloat16,
                           wmma::row_major> fa[2];
#pragma unroll
            for (int i = 0; i < 2; i++)
                wmma::load_matrix_sync(fa[i],
                    Ap + (wm * 32 + i * 16) * A_LD + k0, A_LD);
#pragma unroll
            for (int jn = 0; jn < 4; jn++) {
                wmma::fragment<wmma::matrix_b, 16, 16, 16, __nv_bfloat16,
                               wmma::row_major> fb;
                wmma::load_matrix_sync(fb,
                    Bp + k0 * B_LD + wn * 64 + jn * 16, B_LD);
#pragma unroll
                for (int i = 0; i < 2; i++)
                    wmma::mma_sync(acc[i][jn], fa[i], fb, acc[i][jn]);
            }
        }
    }

    // --- stage to smem (f32, coalescable) then float4 STG
    __syncthreads();
    float* so = reinterpret_cast<float*>(smem);
#pragma unroll
    for (int i = 0; i < 2; i++)
#pragma unroll
        for (int jn = 0; jn < 4; jn++)
            wmma::store_matrix_sync(
                so + (wm * 32 + i * 16) * STG_LD + wn * 64 + jn * 16,
                acc[i][jn], STG_LD, wmma::mem_row_major);
    __syncthreads();

    for (int idx = tid; idx < 4096; idx += 256) {
        int r = idx >> 5, c4 = idx & 31;
        float4 v = *reinterpret_cast<const float4*>(so + r * STG_LD + c4 * 4);
        *reinterpret_cast<float4*>(
            g_kproj + (((size_t)(m0 + r)) * 8 + j) * 128 + c4 * 4) = v;
    }
}

// ---------------------------------------------------------------------------
// Kernel 2: MLP per chain (q@W1q GEMM, kproj gather, gelu, @W2). 75us.
// ---------------------------------------------------------------------------
__global__ __launch_bounds__(256, 2) void chain_kernel(
    const float* __restrict__ q,
    const int*   __restrict__ batch_idx,
    const int*   __restrict__ count,
    const float* __restrict__ W1,
    const float* __restrict__ b1,
    const float* __restrict__ W2,
    const float* __restrict__ b2,
    float* __restrict__ out)
{
    __shared__ float sA[64][36];
    __shared__ float sB[32][128];
    __shared__ float sW1last[128], sB1[128], sW2[128];
    __shared__ int   sIdx[64][8];
    __shared__ int   sN[64], sBatch[64];
    __shared__ float sLogc[64];

    const int tid = threadIdx.x;
    const int c0  = blockIdx.x * 64;

    if (tid < 128) {
        sW1last[tid] = W1[576 * 128 + tid];
        sB1[tid]     = b1[tid];
        sW2[tid]     = W2[tid];
    }
    if (tid < 64) {
        sBatch[tid] = batch_idx[c0 + tid];
        sLogc[tid]  = log1pf((float)count[c0 + tid]);
        sN[tid]     = g_seln[c0 + tid];
    }
    {
        int f = tid;
        sIdx[f >> 2][(f & 3) * 2]     = g_selidx[(size_t)c0 * 8 + f * 2];
        sIdx[f >> 2][(f & 3) * 2 + 1] = g_selidx[(size_t)c0 * 8 + f * 2 + 1];
    }

    const int tr = tid >> 4, tc = tid & 15;
    float acc[4][8];
#pragma unroll
    for (int i = 0; i < 4; i++)
#pragma unroll
        for (int u = 0; u < 8; u++) acc[i][u] = 0.f;

#pragma unroll
    for (int kc = 0; kc < 2; kc++) {
#pragma unroll
        for (int s = 0; s < 2; s++) {
            int f = tid + 256 * s;
            int r = f >> 3, c4 = f & 7;
            float4 vv = *reinterpret_cast<const float4*>(
                q + (size_t)(c0 + r) * 64 + kc * 32 + c4 * 4);
            *reinterpret_cast<float4*>(&sA[r][c4 * 4]) = vv;
        }
#pragma unroll
        for (int s = 0; s < 4; s++) {
            int f = tid + 256 * s;
            int d = f >> 5, c4 = f & 31;
            *reinterpret_cast<float4*>(&sB[d][c4 * 4]) =
                *reinterpret_cast<const float4*>(
                    W1 + (size_t)(kc * 32 + d) * 128 + c4 * 4);
        }
        __syncthreads();
#pragma unroll
        for (int kk = 0; kk < 32; kk++) {
            float ra[4];
#pragma unroll
            for (int i = 0; i < 4; i++) ra[i] = sA[tr * 4 + i][kk];
            float4 w0 = *reinterpret_cast<const float4*>(&sB[kk][tc * 8]);
            float4 w1 = *reinterpret_cast<const float4*>(&sB[kk][tc * 8 + 4]);
            float rb[8] = {w0.x, w0.y, w0.z, w0.w, w1.x, w1.y, w1.z, w1.w};
#pragma unroll
            for (int i = 0; i < 4; i++)
#pragma unroll
                for (int u = 0; u < 8; u++)
                    acc[i][u] = fmaf(ra[i], rb[u], acc[i][u]);
        }
        __syncthreads();
    }

    float wl[8], bb1[8];
#pragma unroll
    for (int u = 0; u < 8; u++) {
        wl[u]  = sW1last[tc * 8 + u];
        bb1[u] = sB1[tc * 8 + u];
    }

#pragma unroll
    for (int i = 0; i < 4; i++) {
        const int cl = tr * 4 + i;
        const int n  = sN[cl];
        const int bb = sBatch[cl];
        const float lc = sLogc[cl];
#pragma unroll
        for (int u = 0; u < 8; u++)
            acc[i][u] = acc[i][u] + bb1[u] + lc * wl[u];
        for (int jj = 0; jj < n; jj++) {
            size_t base = (((size_t)bb * 512 + sIdx[cl][jj]) * 8 + jj) * 128 + tc * 8;
            float4 g0 = *reinterpret_cast<const float4*>(g_kproj + base);
            float4 g1 = *reinterpret_cast<const float4*>(g_kproj + base + 4);
            acc[i][0] += g0.x; acc[i][1] += g0.y; acc[i][2] += g0.z; acc[i][3] += g0.w;
            acc[i][4] += g1.x; acc[i][5] += g1.y; acc[i][6] += g1.z; acc[i][7] += g1.w;
        }
    }

#pragma unroll
    for (int i = 0; i < 4; i++)
#pragma unroll
        for (int u = 0; u < 8; u++) {
            float x = acc[i][u];
            acc[i][u] = 0.5f * x * (1.0f + erff(x * 0.70710678118654752440f));
        }

    const float b2v = b2[0];
#pragma unroll
    for (int i = 0; i < 4; i++) {
        float p = 0.f;
#pragma unroll
        for (int u = 0; u < 8; u++) p = fmaf(acc[i][u], sW2[tc * 8 + u], p);
#pragma unroll
        for (int off = 8; off; off >>= 1)
            p += __shfl_down_sync(0xffffffffu, p, off, 16);
        if (tc == 0) out[c0 + tr * 4 + i] = p + b2v;
    }
}

// ---------------------------------------------------------------------------
extern "C" void kernel_launch(void* const* d_in, const int* in_sizes, int n_in,
                              void* d_out, int out_size)
{
    const float* q         = (const float*)d_in[0];
    const float* kmat      = (const float*)d_in[1];
    const int*   batch_idx = (const int*)d_in[2];
    const int*   mask      = (const int*)d_in[3];
    const int*   count     = (const int*)d_in[4];
    const float* rank      = (const float*)d_in[5];
    const float* W1        = (const float*)d_in[6];
    const float* b1        = (const float*)d_in[7];
    const float* W2        = (const float*)d_in[8];
    const float* b2        = (const float*)d_in[9];
    float* out = (float*)d_out;

    cudaFuncSetAttribute(kproj_wmma_kernel,
                         cudaFuncAttributeMaxDynamicSharedMemorySize, KP_SMEM);

    select_kernel<<<512, 256>>>(mask, rank);
    kproj_wmma_kernel<<<dim3(256, 8), 256, KP_SMEM>>>(kmat, W1);
    chain_kernel<<<1024, 256>>>(q, batch_idx, count, W1, b1, W2, b2, out);
}

// round 6
// speedup vs baseline: 1.3235x; 1.1121x over previous
#include <cuda_runtime.h>
#include <cuda_bf16.h>
#include <mma.h>
#include <float.h>
#include <math.h>
#include <stdint.h>

#define NCH 65536
#define BB  64
#define LL  512
#define MS  8
#define HID 128

__device__ float g_kproj[(size_t)BB * LL * MS * HID];   // 134 MB scratch
__device__ int   g_selidx[(size_t)NCH * MS];
__device__ int   g_seln[NCH];
// pre-split bf16 hi/lo operands
__device__ __nv_bfloat16 g_khi[(size_t)BB * LL * 64];
__device__ __nv_bfloat16 g_klo[(size_t)BB * LL * 64];
__device__ __nv_bfloat16 g_w1hi[577 * 128];
__device__ __nv_bfloat16 g_w1lo[577 * 128];

using namespace nvcuda;

// order-preserving float->u32 (monotonic); masked entries use 0
__device__ __forceinline__ unsigned f2u(float f) {
    unsigned u = __float_as_uint(f);
    return (u & 0x80000000u) ? ~u : (u | 0x80000000u);
}

// ---------------------------------------------------------------------------
// Split kernels: fp32 -> bf16 hi + bf16 lo (residual)
// ---------------------------------------------------------------------------
__global__ void ksplit_kernel(const float* __restrict__ kmat)
{
    const int nf4 = (BB * LL * 64) / 4;    // 524288
    for (int i = blockIdx.x * blockDim.x + threadIdx.x; i < nf4;
         i += gridDim.x * blockDim.x) {
        float4 v = reinterpret_cast<const float4*>(kmat)[i];
        float f[4] = {v.x, v.y, v.z, v.w};
        __nv_bfloat16 h[4], l[4];
#pragma unroll
        for (int e = 0; e < 4; e++) {
            h[e] = __float2bfloat16(f[e]);
            l[e] = __float2bfloat16(f[e] - __bfloat162float(h[e]));
        }
        __nv_bfloat162 h01; h01.x = h[0]; h01.y = h[1];
        __nv_bfloat162 h23; h23.x = h[2]; h23.y = h[3];
        __nv_bfloat162 l01; l01.x = l[0]; l01.y = l[1];
        __nv_bfloat162 l23; l23.x = l[2]; l23.y = l[3];
        reinterpret_cast<__nv_bfloat162*>(g_khi)[i * 2]     = h01;
        reinterpret_cast<__nv_bfloat162*>(g_khi)[i * 2 + 1] = h23;
        reinterpret_cast<__nv_bfloat162*>(g_klo)[i * 2]     = l01;
        reinterpret_cast<__nv_bfloat162*>(g_klo)[i * 2 + 1] = l23;
    }
}

__global__ void w1split_kernel(const float* __restrict__ W1)
{
    const int n = 577 * 128;
    for (int i = blockIdx.x * blockDim.x + threadIdx.x; i < n;
         i += gridDim.x * blockDim.x) {
        float f = W1[i];
        __nv_bfloat16 h = __float2bfloat16(f);
        g_w1hi[i] = h;
        g_w1lo[i] = __float2bfloat16(f - __bfloat162float(h));
    }
}

// ---------------------------------------------------------------------------
// Kernel 0: top-8 selection, incremental top-3 per lane + consumed-bitmask
// epilogue (no ids broadcast, no sort). grid 512 x 256; warp = 16 chains.
// ---------------------------------------------------------------------------
__global__ __launch_bounds__(256) void select_kernel(
    const int* __restrict__ mask, const float* __restrict__ rank)
{
    const int tid = threadIdx.x;
    const int w = tid >> 5, lane = tid & 31;
    const unsigned full = 0xffffffffu;

    for (int cc = 0; cc < 16; cc++) {
        const int chain = (blockIdx.x * 8 + w) * 16 + cc;
        const float* sc = rank + (size_t)chain * 512 + lane * 16;
        const int4*  mk = reinterpret_cast<const int4*>(
                              mask + (size_t)chain * 512) + lane * 4;
        unsigned key[16];
        unsigned m1 = 0, m2 = 0, m3 = 0;
        int p1 = 0, p2 = 0, p3 = 0;
        int cnt = 0;
#pragma unroll
        for (int g = 0; g < 4; g++) {
            int4   mw = mk[g];
            float4 s  = *reinterpret_cast<const float4*>(sc + g * 4);
            int   me[4] = {mw.x, mw.y, mw.z, mw.w};
            float vv[4] = {s.x, s.y, s.z, s.w};
#pragma unroll
            for (int e = 0; e < 4; e++) {
                const int i = g * 4 + e;
                bool mm = (me[e] != 0);
                unsigned k = mm ? f2u(vv[e]) : 0u;
                key[i] = k;
                cnt += mm ? 1 : 0;
                // branchless top-3 insert (value+pos)
                bool g1 = k > m1, g2 = k > m2, g3 = k > m3;
                m3 = g3 ? (g2 ? m2 : k) : m3;  p3 = g3 ? (g2 ? p2 : i) : p3;
                m2 = g2 ? (g1 ? m1 : k) : m2;  p2 = g2 ? (g1 ? p1 : i) : p2;
                m1 = g1 ? k : m1;              p1 = g1 ? i : p1;
            }
        }
        int tot  = __reduce_add_sync(full, cnt);
        int nsel = tot < 8 ? tot : 8;

        unsigned cons = 0;
#pragma unroll
        for (int t = 0; t < 8; t++) {
            unsigned m = __reduce_max_sync(full, m1);
            unsigned bal = __ballot_sync(full, m1 == m);
            int src = __ffs(bal) - 1;
            if (m != 0u && lane == src) {
                cons |= 1u << p1;
                m1 = m2; p1 = p2; m2 = m3; p2 = p3; m3 = 0; p3 = 0;
                if (m1 == 0u) {   // tracked set exhausted: rare rescan
#pragma unroll
                    for (int i = 0; i < 16; i++) {
                        unsigned k = ((cons >> i) & 1u) ? 0u : key[i];
                        bool g1 = k > m1, g2 = k > m2, g3 = k > m3;
                        m3 = g3 ? (g2 ? m2 : k) : m3;  p3 = g3 ? (g2 ? p2 : i) : p3;
                        m2 = g2 ? (g1 ? m1 : k) : m2;  p2 = g2 ? (g1 ? p1 : i) : p2;
                        m1 = g1 ? k : m1;              p1 = g1 ? i : p1;
                    }
                }
            }
        }

        // epilogue: sorted picks = lane-major order of consumed bits
        int my = __popc(cons);
        int pre = my;
#pragma unroll
        for (int off = 1; off < 32; off <<= 1) {
            int v = __shfl_up_sync(full, pre, off);
            if (lane >= off) pre += v;
        }
        pre -= my;           // exclusive prefix
        if (lane == 0) g_seln[chain] = nsel;
        unsigned c = cons;
        int s = pre;
        while (c) {
            int i = __ffs(c) - 1;
            c &= c - 1;
            g_selidx[(size_t)chain * 8 + s] = lane * 16 + i;
            s++;
        }
    }
}

// ---------------------------------------------------------------------------
// Kernel 1: kproj via WMMA bf16x3, fragments loaded straight from global
// (pre-split hi/lo). grid (256, 8), 256 thr; CTA = 128 rows x 128 cols, K=64.
// ---------------------------------------------------------------------------
#define STG_LD  132
#define KP_SMEM (128 * STG_LD * 4)

__global__ __launch_bounds__(256) void kproj_wmma_kernel()
{
    extern __shared__ float so[];
    const int tid = threadIdx.x;
    const int m0  = blockIdx.x * 128;
    const int j   = blockIdx.y;
    const int w   = tid >> 5;
    const int wm  = w >> 1, wn = w & 1;

    wmma::fragment<wmma::accumulator, 16, 16, 16, float> acc[2][4];
#pragma unroll
    for (int i = 0; i < 2; i++)
#pragma unroll
        for (int jn = 0; jn < 4; jn++) wmma::fill_fragment(acc[i][jn], 0.f);

    const __nv_bfloat16* Bh = g_w1hi + (size_t)(64 + j * 64) * 128;
    const __nv_bfloat16* Bl = g_w1lo + (size_t)(64 + j * 64) * 128;

#pragma unroll
    for (int k0 = 0; k0 < 64; k0 += 16) {
        wmma::fragment<wmma::matrix_a, 16, 16, 16, __nv_bfloat16,
                       wmma::row_major> fah[2], fal[2];
#pragma unroll
        for (int i = 0; i < 2; i++) {
            size_t ab = (size_t)(m0 + wm * 32 + i * 16) * 64 + k0;
            wmma::load_matrix_sync(fah[i], g_khi + ab, 64);
            wmma::load_matrix_sync(fal[i], g_klo + ab, 64);
        }
#pragma unroll
        for (int jn = 0; jn < 4; jn++) {
            wmma::fragment<wmma::matrix_b, 16, 16, 16, __nv_bfloat16,
                           wmma::row_major> fbh, fbl;
            wmma::load_matrix_sync(fbh, Bh + (size_t)k0 * 128 + wn * 64 + jn * 16, 128);
            wmma::load_matrix_sync(fbl, Bl + (size_t)k0 * 128 + wn * 64 + jn * 16, 128);
#pragma unroll
            for (int i = 0; i < 2; i++) {
                wmma::mma_sync(acc[i][jn], fah[i], fbh, acc[i][jn]);
                wmma::mma_sync(acc[i][jn], fah[i], fbl, acc[i][jn]);
                wmma::mma_sync(acc[i][jn], fal[i], fbh, acc[i][jn]);
            }
        }
    }

    // stage to smem then coalesced float4 stores
#pragma unroll
    for (int i = 0; i < 2; i++)
#pragma unroll
        for (int jn = 0; jn < 4; jn++)
            wmma::store_matrix_sync(
                so + (wm * 32 + i * 16) * STG_LD + wn * 64 + jn * 16,
                acc[i][jn], STG_LD, wmma::mem_row_major);
    __syncthreads();

    for (int idx = tid; idx < 4096; idx += 256) {
        int r = idx >> 5, c4 = idx & 31;
        float4 v = *reinterpret_cast<const float4*>(so + r * STG_LD + c4 * 4);
        *reinterpret_cast<float4*>(
            g_kproj + (((size_t)(m0 + r)) * 8 + j) * 128 + c4 * 4) = v;
    }
}

// ---------------------------------------------------------------------------
// Kernel 2: MLP per chain (q@W1q GEMM, kproj gather, gelu, @W2).
// ---------------------------------------------------------------------------
__global__ __launch_bounds__(256, 2) void chain_kernel(
    const float* __restrict__ q,
    const int*   __restrict__ batch_idx,
    const int*   __restrict__ count,
    const float* __restrict__ W1,
    const float* __restrict__ b1,
    const float* __restrict__ W2,
    const float* __restrict__ b2,
    float* __restrict__ out)
{
    __shared__ float sA[64][36];
    __shared__ float sB[32][128];
    __shared__ float sW1last[128], sB1[128], sW2[128];
    __shared__ int   sIdx[64][8];
    __shared__ int   sN[64], sBatch[64];
    __shared__ float sLogc[64];

    const int tid = threadIdx.x;
    const int c0  = blockIdx.x * 64;

    if (tid < 128) {
        sW1last[tid] = W1[576 * 128 + tid];
        sB1[tid]     = b1[tid];
        sW2[tid]     = W2[tid];
    }
    if (tid < 64) {
        sBatch[tid] = batch_idx[c0 + tid];
        sLogc[tid]  = log1pf((float)count[c0 + tid]);
        sN[tid]     = g_seln[c0 + tid];
    }
    {
        int f = tid;
        sIdx[f >> 2][(f & 3) * 2]     = g_selidx[(size_t)c0 * 8 + f * 2];
        sIdx[f >> 2][(f & 3) * 2 + 1] = g_selidx[(size_t)c0 * 8 + f * 2 + 1];
    }

    const int tr = tid >> 4, tc = tid & 15;
    float acc[4][8];
#pragma unroll
    for (int i = 0; i < 4; i++)
#pragma unroll
        for (int u = 0; u < 8; u++) acc[i][u] = 0.f;

#pragma unroll
    for (int kc = 0; kc < 2; kc++) {
#pragma unroll
        for (int s = 0; s < 2; s++) {
            int f = tid + 256 * s;
            int r = f >> 3, c4 = f & 7;
            float4 vv = *reinterpret_cast<const float4*>(
                q + (size_t)(c0 + r) * 64 + kc * 32 + c4 * 4);
            *reinterpret_cast<float4*>(&sA[r][c4 * 4]) = vv;
        }
#pragma unroll
        for (int s = 0; s < 4; s++) {
            int f = tid + 256 * s;
            int d = f >> 5, c4 = f & 31;
            *reinterpret_cast<float4*>(&sB[d][c4 * 4]) =
                *reinterpret_cast<const float4*>(
                    W1 + (size_t)(kc * 32 + d) * 128 + c4 * 4);
        }
        __syncthreads();
#pragma unroll
        for (int kk = 0; kk < 32; kk++) {
            float ra[4];
#pragma unroll
            for (int i = 0; i < 4; i++) ra[i] = sA[tr * 4 + i][kk];
            float4 w0 = *reinterpret_cast<const float4*>(&sB[kk][tc * 8]);
            float4 w1 = *reinterpret_cast<const float4*>(&sB[kk][tc * 8 + 4]);
            float rb[8] = {w0.x, w0.y, w0.z, w0.w, w1.x, w1.y, w1.z, w1.w};
#pragma unroll
            for (int i = 0; i < 4; i++)
#pragma unroll
                for (int u = 0; u < 8; u++)
                    acc[i][u] = fmaf(ra[i], rb[u], acc[i][u]);
        }
        __syncthreads();
    }

    float wl[8], bb1[8];
#pragma unroll
    for (int u = 0; u < 8; u++) {
        wl[u]  = sW1last[tc * 8 + u];
        bb1[u] = sB1[tc * 8 + u];
    }

#pragma unroll
    for (int i = 0; i < 4; i++) {
        const int cl = tr * 4 + i;
        const int n  = sN[cl];
        const int bb = sBatch[cl];
        const float lc = sLogc[cl];
#pragma unroll
        for (int u = 0; u < 8; u++)
            acc[i][u] = acc[i][u] + bb1[u] + lc * wl[u];
        for (int jj = 0; jj < n; jj++) {
            size_t base = (((size_t)bb * 512 + sIdx[cl][jj]) * 8 + jj) * 128 + tc * 8;
            float4 g0 = *reinterpret_cast<const float4*>(g_kproj + base);
            float4 g1 = *reinterpret_cast<const float4*>(g_kproj + base + 4);
            acc[i][0] += g0.x; acc[i][1] += g0.y; acc[i][2] += g0.z; acc[i][3] += g0.w;
            acc[i][4] += g1.x; acc[i][5] += g1.y; acc[i][6] += g1.z; acc[i][7] += g1.w;
        }
    }

#pragma unroll
    for (int i = 0; i < 4; i++)
#pragma unroll
        for (int u = 0; u < 8; u++) {
            float x = acc[i][u];
            acc[i][u] = 0.5f * x * (1.0f + erff(x * 0.70710678118654752440f));
        }

    const float b2v = b2[0];
#pragma unroll
    for (int i = 0; i < 4; i++) {
        float p = 0.f;
#pragma unroll
        for (int u = 0; u < 8; u++) p = fmaf(acc[i][u], sW2[tc * 8 + u], p);
#pragma unroll
        for (int off = 8; off; off >>= 1)
            p += __shfl_down_sync(0xffffffffu, p, off, 16);
        if (tc == 0) out[c0 + tr * 4 + i] = p + b2v;
    }
}

// ---------------------------------------------------------------------------
extern "C" void kernel_launch(void* const* d_in, const int* in_sizes, int n_in,
                              void* d_out, int out_size)
{
    const float* q         = (const float*)d_in[0];
    const float* kmat      = (const float*)d_in[1];
    const int*   batch_idx = (const int*)d_in[2];
    const int*   mask      = (const int*)d_in[3];
    const int*   count     = (const int*)d_in[4];
    const float* rank      = (const float*)d_in[5];
    const float* W1        = (const float*)d_in[6];
    const float* b1        = (const float*)d_in[7];
    const float* W2        = (const float*)d_in[8];
    const float* b2        = (const float*)d_in[9];
    float* out = (float*)d_out;

    cudaFuncSetAttribute(kproj_wmma_kernel,
                         cudaFuncAttributeMaxDynamicSharedMemorySize, KP_SMEM);

    ksplit_kernel<<<512, 256>>>(kmat);
    w1split_kernel<<<64, 256>>>(W1);
    select_kernel<<<512, 256>>>(mask, rank);
    kproj_wmma_kernel<<<dim3(256, 8), 256, KP_SMEM>>>();
    chain_kernel<<<1024, 256>>>(q, batch_idx, count, W1, b1, W2, b2, out);
}

// round 7
// speedup vs baseline: 1.7451x; 1.3186x over previous
#include <cuda_runtime.h>
#include <cuda_bf16.h>
#include <mma.h>
#include <float.h>
#include <math.h>
#include <stdint.h>

#define NCH 65536
#define BB  64
#define LL  512
#define MS  8
#define HID 128

__device__ float g_kproj[(size_t)BB * LL * MS * HID];   // 134 MB scratch
__device__ int   g_selidx[(size_t)NCH * MS];
__device__ int   g_seln[NCH];
// pre-split bf16 hi/lo operands
__device__ __nv_bfloat16 g_khi[(size_t)BB * LL * 64];
__device__ __nv_bfloat16 g_klo[(size_t)BB * LL * 64];
__device__ __nv_bfloat16 g_w1hi[577 * 128];
__device__ __nv_bfloat16 g_w1lo[577 * 128];

using namespace nvcuda;

// order-preserving float->u32 (monotonic); masked entries use 0
__device__ __forceinline__ unsigned f2u(float f) {
    unsigned u = __float_as_uint(f);
    return (u & 0x80000000u) ? ~u : (u | 0x80000000u);
}

// ---------------------------------------------------------------------------
// Split kernels: fp32 -> bf16 hi + bf16 lo (residual)
// ---------------------------------------------------------------------------
__global__ void ksplit_kernel(const float* __restrict__ kmat)
{
    const int nf4 = (BB * LL * 64) / 4;    // 524288
    for (int i = blockIdx.x * blockDim.x + threadIdx.x; i < nf4;
         i += gridDim.x * blockDim.x) {
        float4 v = reinterpret_cast<const float4*>(kmat)[i];
        float f[4] = {v.x, v.y, v.z, v.w};
        __nv_bfloat16 h[4], l[4];
#pragma unroll
        for (int e = 0; e < 4; e++) {
            h[e] = __float2bfloat16(f[e]);
            l[e] = __float2bfloat16(f[e] - __bfloat162float(h[e]));
        }
        __nv_bfloat162 h01; h01.x = h[0]; h01.y = h[1];
        __nv_bfloat162 h23; h23.x = h[2]; h23.y = h[3];
        __nv_bfloat162 l01; l01.x = l[0]; l01.y = l[1];
        __nv_bfloat162 l23; l23.x = l[2]; l23.y = l[3];
        reinterpret_cast<__nv_bfloat162*>(g_khi)[i * 2]     = h01;
        reinterpret_cast<__nv_bfloat162*>(g_khi)[i * 2 + 1] = h23;
        reinterpret_cast<__nv_bfloat162*>(g_klo)[i * 2]     = l01;
        reinterpret_cast<__nv_bfloat162*>(g_klo)[i * 2 + 1] = l23;
    }
}

__global__ void w1split_kernel(const float* __restrict__ W1)
{
    const int n = 577 * 128;
    for (int i = blockIdx.x * blockDim.x + threadIdx.x; i < n;
         i += gridDim.x * blockDim.x) {
        float f = W1[i];
        __nv_bfloat16 h = __float2bfloat16(f);
        g_w1hi[i] = h;
        g_w1lo[i] = __float2bfloat16(f - __bfloat162float(h));
    }
}

// ---------------------------------------------------------------------------
// Kernel 0: top-8 selection, incremental top-3 per lane + consumed-bitmask
// epilogue. grid 512 x 256; warp = 16 chains.
// ---------------------------------------------------------------------------
__global__ __launch_bounds__(256) void select_kernel(
    const int* __restrict__ mask, const float* __restrict__ rank)
{
    const int tid = threadIdx.x;
    const int w = tid >> 5, lane = tid & 31;
    const unsigned full = 0xffffffffu;

    for (int cc = 0; cc < 16; cc++) {
        const int chain = (blockIdx.x * 8 + w) * 16 + cc;
        const float* sc = rank + (size_t)chain * 512 + lane * 16;
        const int4*  mk = reinterpret_cast<const int4*>(
                              mask + (size_t)chain * 512) + lane * 4;
        unsigned key[16];
        unsigned m1 = 0, m2 = 0, m3 = 0;
        int p1 = 0, p2 = 0, p3 = 0;
        int cnt = 0;
#pragma unroll
        for (int g = 0; g < 4; g++) {
            int4   mw = mk[g];
            float4 s  = *reinterpret_cast<const float4*>(sc + g * 4);
            int   me[4] = {mw.x, mw.y, mw.z, mw.w};
            float vv[4] = {s.x, s.y, s.z, s.w};
#pragma unroll
            for (int e = 0; e < 4; e++) {
                const int i = g * 4 + e;
                bool mm = (me[e] != 0);
                unsigned k = mm ? f2u(vv[e]) : 0u;
                key[i] = k;
                cnt += mm ? 1 : 0;
                bool g1 = k > m1, g2 = k > m2, g3 = k > m3;
                m3 = g3 ? (g2 ? m2 : k) : m3;  p3 = g3 ? (g2 ? p2 : i) : p3;
                m2 = g2 ? (g1 ? m1 : k) : m2;  p2 = g2 ? (g1 ? p1 : i) : p2;
                m1 = g1 ? k : m1;              p1 = g1 ? i : p1;
            }
        }
        int tot  = __reduce_add_sync(full, cnt);
        int nsel = tot < 8 ? tot : 8;

        unsigned cons = 0;
#pragma unroll
        for (int t = 0; t < 8; t++) {
            unsigned m = __reduce_max_sync(full, m1);
            unsigned bal = __ballot_sync(full, m1 == m);
            int src = __ffs(bal) - 1;
            if (m != 0u && lane == src) {
                cons |= 1u << p1;
                m1 = m2; p1 = p2; m2 = m3; p2 = p3; m3 = 0; p3 = 0;
                if (m1 == 0u) {   // tracked set exhausted: rare rescan
#pragma unroll
                    for (int i = 0; i < 16; i++) {
                        unsigned k = ((cons >> i) & 1u) ? 0u : key[i];
                        bool g1 = k > m1, g2 = k > m2, g3 = k > m3;
                        m3 = g3 ? (g2 ? m2 : k) : m3;  p3 = g3 ? (g2 ? p2 : i) : p3;
                        m2 = g2 ? (g1 ? m1 : k) : m2;  p2 = g2 ? (g1 ? p1 : i) : p2;
                        m1 = g1 ? k : m1;              p1 = g1 ? i : p1;
                    }
                }
            }
        }

        // epilogue: sorted picks = lane-major order of consumed bits
        int my = __popc(cons);
        int pre = my;
#pragma unroll
        for (int off = 1; off < 32; off <<= 1) {
            int v = __shfl_up_sync(full, pre, off);
            if (lane >= off) pre += v;
        }
        pre -= my;
        if (lane == 0) g_seln[chain] = nsel;
        unsigned c = cons;
        int s = pre;
        while (c) {
            int i = __ffs(c) - 1;
            c &= c - 1;
            g_selidx[(size_t)chain * 8 + s] = lane * 16 + i;
            s++;
        }
    }
}

// ---------------------------------------------------------------------------
// Kernel 1: kproj via WMMA bf16x3 with SMEM-staged inputs (coalesced uint4
// from pre-split buffers -> ldmatrix-path fragment loads). Output staging is
// aliased over the dead A/B input region. grid (256, 8), 256 threads.
// ---------------------------------------------------------------------------
#define A_LD 72      // bf16 elems (row stride 144B, 16B-aligned)
#define B_LD 136     // bf16 elems (row stride 272B, 16B-aligned)
#define OFF_AH 0
#define OFF_AL 18432
#define OFF_BH 36864
#define OFF_BL 54272
#define KP_SMEM 71680
#define STG_LD  132

__global__ __launch_bounds__(256, 2) void kproj_wmma_kernel()
{
    extern __shared__ char smem[];
    __nv_bfloat16* Ah = reinterpret_cast<__nv_bfloat16*>(smem + OFF_AH);
    __nv_bfloat16* Al = reinterpret_cast<__nv_bfloat16*>(smem + OFF_AL);
    __nv_bfloat16* Bh = reinterpret_cast<__nv_bfloat16*>(smem + OFF_BH);
    __nv_bfloat16* Bl = reinterpret_cast<__nv_bfloat16*>(smem + OFF_BL);

    const int tid = threadIdx.x;
    const int m0  = blockIdx.x * 128;
    const int j   = blockIdx.y;
    const int w   = tid >> 5;
    const int wm  = w >> 1, wn = w & 1;

    // --- stage A: 128x64 bf16 hi+lo = 1024 uint4 each
    for (int idx = tid; idx < 1024; idx += 256) {
        int r = idx >> 3, c8 = idx & 7;
        size_t src = (size_t)(m0 + r) * 64 + c8 * 8;
        *reinterpret_cast<uint4*>(Ah + r * A_LD + c8 * 8) =
            *reinterpret_cast<const uint4*>(g_khi + src);
        *reinterpret_cast<uint4*>(Al + r * A_LD + c8 * 8) =
            *reinterpret_cast<const uint4*>(g_klo + src);
    }
    // --- stage B: 64x128 bf16 hi+lo = 1024 uint4 each
    for (int idx = tid; idx < 1024; idx += 256) {
        int r = idx >> 4, c8 = idx & 15;
        size_t src = (size_t)(64 + j * 64 + r) * 128 + c8 * 8;
        *reinterpret_cast<uint4*>(Bh + r * B_LD + c8 * 8) =
            *reinterpret_cast<const uint4*>(g_w1hi + src);
        *reinterpret_cast<uint4*>(Bl + r * B_LD + c8 * 8) =
            *reinterpret_cast<const uint4*>(g_w1lo + src);
    }
    __syncthreads();

    wmma::fragment<wmma::accumulator, 16, 16, 16, float> acc[2][4];
#pragma unroll
    for (int i = 0; i < 2; i++)
#pragma unroll
        for (int jn = 0; jn < 4; jn++) wmma::fill_fragment(acc[i][jn], 0.f);

#pragma unroll
    for (int k0 = 0; k0 < 64; k0 += 16) {
        wmma::fragment<wmma::matrix_a, 16, 16, 16, __nv_bfloat16,
                       wmma::row_major> fah[2], fal[2];
#pragma unroll
        for (int i = 0; i < 2; i++) {
            int ab = (wm * 32 + i * 16) * A_LD + k0;
            wmma::load_matrix_sync(fah[i], Ah + ab, A_LD);
            wmma::load_matrix_sync(fal[i], Al + ab, A_LD);
        }
#pragma unroll
        for (int jn = 0; jn < 4; jn++) {
            wmma::fragment<wmma::matrix_b, 16, 16, 16, __nv_bfloat16,
                           wmma::row_major> fbh, fbl;
            int bb = k0 * B_LD + wn * 64 + jn * 16;
            wmma::load_matrix_sync(fbh, Bh + bb, B_LD);
            wmma::load_matrix_sync(fbl, Bl + bb, B_LD);
#pragma unroll
            for (int i = 0; i < 2; i++) {
                wmma::mma_sync(acc[i][jn], fah[i], fbh, acc[i][jn]);
                wmma::mma_sync(acc[i][jn], fah[i], fbl, acc[i][jn]);
                wmma::mma_sync(acc[i][jn], fal[i], fbh, acc[i][jn]);
            }
        }
    }

    // --- output staging aliased over (now dead) A/B input region
    __syncthreads();
    float* so = reinterpret_cast<float*>(smem);
#pragma unroll
    for (int i = 0; i < 2; i++)
#pragma unroll
        for (int jn = 0; jn < 4; jn++)
            wmma::store_matrix_sync(
                so + (wm * 32 + i * 16) * STG_LD + wn * 64 + jn * 16,
                acc[i][jn], STG_LD, wmma::mem_row_major);
    __syncthreads();

    for (int idx = tid; idx < 4096; idx += 256) {
        int r = idx >> 5, c4 = idx & 31;
        float4 v = *reinterpret_cast<const float4*>(so + r * STG_LD + c4 * 4);
        *reinterpret_cast<float4*>(
            g_kproj + (((size_t)(m0 + r)) * 8 + j) * 128 + c4 * 4) = v;
    }
}

// ---------------------------------------------------------------------------
// Kernel 2: MLP per chain (q@W1q GEMM, kproj gather, gelu, @W2).
// ---------------------------------------------------------------------------
__global__ __launch_bounds__(256, 2) void chain_kernel(
    const float* __restrict__ q,
    const int*   __restrict__ batch_idx,
    const int*   __restrict__ count,
    const float* __restrict__ W1,
    const float* __restrict__ b1,
    const float* __restrict__ W2,
    const float* __restrict__ b2,
    float* __restrict__ out)
{
    __shared__ float sA[64][36];
    __shared__ float sB[32][128];
    __shared__ float sW1last[128], sB1[128], sW2[128];
    __shared__ int   sIdx[64][8];
    __shared__ int   sN[64], sBatch[64];
    __shared__ float sLogc[64];

    const int tid = threadIdx.x;
    const int c0  = blockIdx.x * 64;

    if (tid < 128) {
        sW1last[tid] = W1[576 * 128 + tid];
        sB1[tid]     = b1[tid];
        sW2[tid]     = W2[tid];
    }
    if (tid < 64) {
        sBatch[tid] = batch_idx[c0 + tid];
        sLogc[tid]  = log1pf((float)count[c0 + tid]);
        sN[tid]     = g_seln[c0 + tid];
    }
    {
        int f = tid;
        sIdx[f >> 2][(f & 3) * 2]     = g_selidx[(size_t)c0 * 8 + f * 2];
        sIdx[f >> 2][(f & 3) * 2 + 1] = g_selidx[(size_t)c0 * 8 + f * 2 + 1];
    }

    const int tr = tid >> 4, tc = tid & 15;
    float acc[4][8];
#pragma unroll
    for (int i = 0; i < 4; i++)
#pragma unroll
        for (int u = 0; u < 8; u++) acc[i][u] = 0.f;

#pragma unroll
    for (int kc = 0; kc < 2; kc++) {
#pragma unroll
        for (int s = 0; s < 2; s++) {
            int f = tid + 256 * s;
            int r = f >> 3, c4 = f & 7;
            float4 vv = *reinterpret_cast<const float4*>(
                q + (size_t)(c0 + r) * 64 + kc * 32 + c4 * 4);
            *reinterpret_cast<float4*>(&sA[r][c4 * 4]) = vv;
        }
#pragma unroll
        for (int s = 0; s < 4; s++) {
            int f = tid + 256 * s;
            int d = f >> 5, c4 = f & 31;
            *reinterpret_cast<float4*>(&sB[d][c4 * 4]) =
                *reinterpret_cast<const float4*>(
                    W1 + (size_t)(kc * 32 + d) * 128 + c4 * 4);
        }
        __syncthreads();
#pragma unroll
        for (int kk = 0; kk < 32; kk++) {
            float ra[4];
#pragma unroll
            for (int i = 0; i < 4; i++) ra[i] = sA[tr * 4 + i][kk];
            float4 w0 = *reinterpret_cast<const float4*>(&sB[kk][tc * 8]);
            float4 w1 = *reinterpret_cast<const float4*>(&sB[kk][tc * 8 + 4]);
            float rb[8] = {w0.x, w0.y, w0.z, w0.w, w1.x, w1.y, w1.z, w1.w};
#pragma unroll
            for (int i = 0; i < 4; i++)
#pragma unroll
                for (int u = 0; u < 8; u++)
                    acc[i][u] = fmaf(ra[i], rb[u], acc[i][u]);
        }
        __syncthreads();
    }

    float wl[8], bb1[8];
#pragma unroll
    for (int u = 0; u < 8; u++) {
        wl[u]  = sW1last[tc * 8 + u];
        bb1[u] = sB1[tc * 8 + u];
    }

#pragma unroll
    for (int i = 0; i < 4; i++) {
        const int cl = tr * 4 + i;
        const int n  = sN[cl];
        const int bb = sBatch[cl];
        const float lc = sLogc[cl];
#pragma unroll
        for (int u = 0; u < 8; u++)
            acc[i][u] = acc[i][u] + bb1[u] + lc * wl[u];
        for (int jj = 0; jj < n; jj++) {
            size_t base = (((size_t)bb * 512 + sIdx[cl][jj]) * 8 + jj) * 128 + tc * 8;
            float4 g0 = *reinterpret_cast<const float4*>(g_kproj + base);
            float4 g1 = *reinterpret_cast<const float4*>(g_kproj + base + 4);
            acc[i][0] += g0.x; acc[i][1] += g0.y; acc[i][2] += g0.z; acc[i][3] += g0.w;
            acc[i][4] += g1.x; acc[i][5] += g1.y; acc[i][6] += g1.z; acc[i][7] += g1.w;
        }
    }

#pragma unroll
    for (int i = 0; i < 4; i++)
#pragma unroll
        for (int u = 0; u < 8; u++) {
            float x = acc[i][u];
            acc[i][u] = 0.5f * x * (1.0f + erff(x * 0.70710678118654752440f));
        }

    const float b2v = b2[0];
#pragma unroll
    for (int i = 0; i < 4; i++) {
        float p = 0.f;
#pragma unroll
        for (int u = 0; u < 8; u++) p = fmaf(acc[i][u], sW2[tc * 8 + u], p);
#pragma unroll
        for (int off = 8; off; off >>= 1)
            p += __shfl_down_sync(0xffffffffu, p, off, 16);
        if (tc == 0) out[c0 + tr * 4 + i] = p + b2v;
    }
}

// ---------------------------------------------------------------------------
extern "C" void kernel_launch(void* const* d_in, const int* in_sizes, int n_in,
                              void* d_out, int out_size)
{
    const float* q         = (const float*)d_in[0];
    const float* kmat      = (const float*)d_in[1];
    const int*   batch_idx = (const int*)d_in[2];
    const int*   mask      = (const int*)d_in[3];
    const int*   count     = (const int*)d_in[4];
    const float* rank      = (const float*)d_in[5];
    const float* W1        = (const float*)d_in[6];
    const float* b1        = (const float*)d_in[7];
    const float* W2        = (const float*)d_in[8];
    const float* b2        = (const float*)d_in[9];
    float* out = (float*)d_out;

    cudaFuncSetAttribute(kproj_wmma_kernel,
                         cudaFuncAttributeMaxDynamicSharedMemorySize, KP_SMEM);

    ksplit_kernel<<<512, 256>>>(kmat);
    w1split_kernel<<<64, 256>>>(W1);
    select_kernel<<<512, 256>>>(mask, rank);
    kproj_wmma_kernel<<<dim3(256, 8), 256, KP_SMEM>>>();
    chain_kernel<<<1024, 256>>>(q, batch_idx, count, W1, b1, W2, b2, out);
}